// round 1
// baseline (speedup 1.0000x reference)
#include <cuda_runtime.h>
#include <math.h>

// Problem shape (fixed by setup_inputs)
#define BB 16
#define NN 4096
#define MM 1024
#define NSPLIT 4
#define NT (NN / NSPLIT)   // 1024 shape points per split

// Key packing: top 22 bits of d2 (sign+exp+13 mantissa bits), low 10 bits = local index
#define KEY_MASK 0xFFFFFC00u
#define IDX_MASK 0x000003FFu

// Accumulator + scratch (static device globals: no allocation allowed)
__device__ double g_acc;
__device__ unsigned int g_p1[BB * MM * NSPLIT];
__device__ unsigned int g_p2[BB * MM * NSPLIT];

__global__ void k_zero() { g_acc = 0.0; }

// branch-free top-2 update on packed keys (positive-float uint ordering)
__device__ __forceinline__ void upd2(unsigned int& b1, unsigned int& b2, unsigned int k) {
    unsigned int mx = max(k, b1);
    b2 = min(b2, mx);
    b1 = min(b1, k);
}

__device__ __forceinline__ float blockSum(float v) {
    #pragma unroll
    for (int o = 16; o; o >>= 1) v += __shfl_xor_sync(0xFFFFFFFFu, v, o);
    __shared__ float ws[32];
    int w = threadIdx.x >> 5, l = threadIdx.x & 31;
    if (l == 0) ws[w] = v;
    __syncthreads();
    int nw = blockDim.x >> 5;
    v = (threadIdx.x < 32) ? ((l < nw) ? ws[l] : 0.0f) : 0.0f;
    if (w == 0) {
        #pragma unroll
        for (int o = 16; o; o >>= 1) v += __shfl_xor_sync(0xFFFFFFFFu, v, o);
    }
    return v;  // valid on thread 0
}

// ---------------------------------------------------------------------------
// K1: per (b, m) partial top-2 over a 1024-point split of N.
// grid = (MM/128 * NSPLIT, BB), block = 128
// ---------------------------------------------------------------------------
__global__ void __launch_bounds__(128) k_skel(const float* __restrict__ shape,
                                              const float* __restrict__ skel) {
    __shared__ float4 sp[NT];
    const int b      = blockIdx.y;
    const int split  = blockIdx.x & (NSPLIT - 1);
    const int mchunk = blockIdx.x >> 2;
    const int m      = mchunk * 128 + threadIdx.x;
    const int nbase  = split * NT;

    for (int i = threadIdx.x; i < NT; i += 128) {
        const float* p = shape + ((size_t)(b * NN + nbase + i)) * 6;
        sp[i] = make_float4(p[0], p[1], p[2], 0.0f);
    }
    __syncthreads();

    const float* s = skel + ((size_t)(b * MM + m)) * 3;
    const float sx = s[0], sy = s[1], sz = s[2];

    unsigned int b1a = ~0u, b2a = ~0u, b1b = ~0u, b2b = ~0u;
    unsigned int b1c = ~0u, b2c = ~0u, b1d = ~0u, b2d = ~0u;

    #pragma unroll 4
    for (int j = 0; j < NT; j += 4) {
        float4 p0 = sp[j + 0], p1 = sp[j + 1], p2 = sp[j + 2], p3 = sp[j + 3];
        float dx0 = p0.x - sx, dy0 = p0.y - sy, dz0 = p0.z - sz;
        float dx1 = p1.x - sx, dy1 = p1.y - sy, dz1 = p1.z - sz;
        float dx2 = p2.x - sx, dy2 = p2.y - sy, dz2 = p2.z - sz;
        float dx3 = p3.x - sx, dy3 = p3.y - sy, dz3 = p3.z - sz;
        float q0 = dx0 * dx0 + dy0 * dy0 + dz0 * dz0;
        float q1 = dx1 * dx1 + dy1 * dy1 + dz1 * dz1;
        float q2 = dx2 * dx2 + dy2 * dy2 + dz2 * dz2;
        float q3 = dx3 * dx3 + dy3 * dy3 + dz3 * dz3;
        upd2(b1a, b2a, (__float_as_uint(q0) & KEY_MASK) | (unsigned)(j + 0));
        upd2(b1b, b2b, (__float_as_uint(q1) & KEY_MASK) | (unsigned)(j + 1));
        upd2(b1c, b2c, (__float_as_uint(q2) & KEY_MASK) | (unsigned)(j + 2));
        upd2(b1d, b2d, (__float_as_uint(q3) & KEY_MASK) | (unsigned)(j + 3));
    }
    // merge the 4 independent top-2 sets into set a
    upd2(b1a, b2a, b1b); upd2(b1a, b2a, b2b);
    upd2(b1a, b2a, b1c); upd2(b1a, b2a, b2c);
    upd2(b1a, b2a, b1d); upd2(b1a, b2a, b2d);

    const int idx = (b * MM + m) * NSPLIT + split;
    g_p1[idx] = b1a;
    g_p2[idx] = b2a;
}

// ---------------------------------------------------------------------------
// K2: per (b, n) min over all M skeleton points -> cd1 term.
// grid = (NN/256, BB), block = 256
// ---------------------------------------------------------------------------
__global__ void __launch_bounds__(256) k_shape(const float* __restrict__ shape,
                                               const float* __restrict__ skel) {
    __shared__ float4 ss[MM];
    const int b = blockIdx.y;
    const int n = blockIdx.x * 256 + threadIdx.x;

    for (int i = threadIdx.x; i < MM; i += 256) {
        const float* s = skel + ((size_t)(b * MM + i)) * 3;
        ss[i] = make_float4(s[0], s[1], s[2], 0.0f);
    }
    __syncthreads();

    const float* p = shape + ((size_t)(b * NN + n)) * 6;
    const float px = p[0], py = p[1], pz = p[2];

    float m0 = 1e30f, m1 = 1e30f, m2 = 1e30f, m3 = 1e30f;
    #pragma unroll 4
    for (int j = 0; j < MM; j += 4) {
        float4 s0 = ss[j + 0], s1 = ss[j + 1], s2 = ss[j + 2], s3 = ss[j + 3];
        float dx0 = px - s0.x, dy0 = py - s0.y, dz0 = pz - s0.z;
        float dx1 = px - s1.x, dy1 = py - s1.y, dz1 = pz - s1.z;
        float dx2 = px - s2.x, dy2 = py - s2.y, dz2 = pz - s2.z;
        float dx3 = px - s3.x, dy3 = py - s3.y, dz3 = pz - s3.z;
        m0 = fminf(m0, dx0 * dx0 + dy0 * dy0 + dz0 * dz0);
        m1 = fminf(m1, dx1 * dx1 + dy1 * dy1 + dz1 * dz1);
        m2 = fminf(m2, dx2 * dx2 + dy2 * dy2 + dz2 * dz2);
        m3 = fminf(m3, dx3 * dx3 + dy3 * dy3 + dz3 * dz3);
    }
    float dmin = fminf(fminf(m0, m1), fminf(m2, m3));
    float val  = 1e-4f * sqrtf(fmaxf(dmin, 1e-12f));

    float bsum = blockSum(val);
    if (threadIdx.x == 0) atomicAdd(&g_acc, (double)bsum);
}

// ---------------------------------------------------------------------------
// K3: merge split partials per (b, m); cd2 + normal-alignment terms.
// grid = BB*MM/256, block = 256
// ---------------------------------------------------------------------------
__global__ void __launch_bounds__(256) k_merge(const float* __restrict__ shape,
                                               const float* __restrict__ nori) {
    const int t = blockIdx.x * 256 + threadIdx.x;  // t = b*MM + m
    const int b = t / MM;

    float d1 = 1e30f, d2v = 1e30f;
    int n1 = 0, n2 = 0;

    #pragma unroll
    for (int s = 0; s < NSPLIT; s++) {
        const int base = t * NSPLIT + s;
        #pragma unroll
        for (int which = 0; which < 2; which++) {
            unsigned int key = which ? g_p2[base] : g_p1[base];
            float df = __uint_as_float(key & KEY_MASK);
            int   nn = (int)(key & IDX_MASK) + s * NT;
            if (df < d1)       { d2v = d1; n2 = n1; d1 = df; n1 = nn; }
            else if (df < d2v) { d2v = df; n2 = nn; }
        }
    }

    float cd = sqrtf(fmaxf(d1, 1e-12f));

    const float* nr = nori + (size_t)t * 3;
    const float* f1 = shape + ((size_t)(b * NN + n1)) * 6 + 3;
    const float* f2 = shape + ((size_t)(b * NN + n2)) * 6 + 3;
    float dot1 = nr[0] * f1[0] + nr[1] * f1[1] + nr[2] * f1[2];
    float dot2 = nr[0] * f2[0] + nr[1] * f2[1] + nr[2] * f2[2];

    float val = 1e-4f * cd + (0.001f / (float)BB) * 0.5f * (fabsf(dot1) + fabsf(dot2));

    float bsum = blockSum(val);
    if (threadIdx.x == 0) atomicAdd(&g_acc, (double)bsum);
}

__global__ void k_fin(float* __restrict__ out) { out[0] = (float)g_acc; }

extern "C" void kernel_launch(void* const* d_in, const int* in_sizes, int n_in,
                              void* d_out, int out_size) {
    const float* shape = (const float*)d_in[0];  // (B, N, 6)
    const float* skel  = (const float*)d_in[1];  // (B, M, 3)
    const float* nori  = (const float*)d_in[2];  // (B, M, 3)
    float* out = (float*)d_out;

    k_zero<<<1, 1>>>();

    dim3 g1(MM / 128 * NSPLIT, BB);
    k_skel<<<g1, 128>>>(shape, skel);

    dim3 g2(NN / 256, BB);
    k_shape<<<g2, 256>>>(shape, skel);

    k_merge<<<BB * MM / 256, 256>>>(shape, nori);

    k_fin<<<1, 1>>>(out);
}

// round 2
// speedup vs baseline: 1.2608x; 1.2608x over previous
#include <cuda_runtime.h>
#include <math.h>

#define BB 16
#define NN 4096
#define MM 1024
#define NSPLIT 4
#define NT (NN / NSPLIT)   // 1024

#define KEY_MASK 0xFFFFFC00u
#define IDX_MASK 0x000003FFu

typedef unsigned long long u64;

// scratch (static device globals: no allocation allowed)
__device__ unsigned int g_p1[BB * MM * NSPLIT];
__device__ unsigned int g_p2[BB * MM * NSPLIT];
__device__ float        g_ps[512];   // shape-part block partials
__device__ float        g_pm[256];   // merge-part block partials
__device__ unsigned int g_cnt = 0;   // self-resetting completion counter

// ---- packed f32x2 helpers (register-pair aliased; no repack cost) ----
__device__ __forceinline__ u64 addx2(u64 a, u64 b) {
    u64 r; asm("add.rn.f32x2 %0,%1,%2;" : "=l"(r) : "l"(a), "l"(b)); return r;
}
__device__ __forceinline__ u64 mulx2(u64 a, u64 b) {
    u64 r; asm("mul.rn.f32x2 %0,%1,%2;" : "=l"(r) : "l"(a), "l"(b)); return r;
}
__device__ __forceinline__ u64 fmx2(u64 a, u64 b, u64 c) {
    u64 r; asm("fma.rn.f32x2 %0,%1,%2,%3;" : "=l"(r) : "l"(a), "l"(b), "l"(c)); return r;
}
__device__ __forceinline__ u64 pk2(float a, float b) {
    u64 r; asm("mov.b64 %0,{%1,%2};" : "=l"(r) : "f"(a), "f"(b)); return r;
}
__device__ __forceinline__ void upku(u64 v, unsigned& a, unsigned& b) {
    asm("mov.b64 {%0,%1},%2;" : "=r"(a), "=r"(b) : "l"(v));
}
__device__ __forceinline__ void upkf(u64 v, float& a, float& b) {
    asm("mov.b64 {%0,%1},%2;" : "=f"(a), "=f"(b) : "l"(v));
}

// branch-free top-2 update on packed keys (positive-float uint ordering)
__device__ __forceinline__ void upd2(unsigned& b1, unsigned& b2, unsigned k) {
    unsigned mx = max(k, b1);
    b2 = min(b2, mx);
    b1 = min(b1, k);
}

__device__ __forceinline__ float blockSum(float v) {
    #pragma unroll
    for (int o = 16; o; o >>= 1) v += __shfl_xor_sync(0xFFFFFFFFu, v, o);
    __shared__ float ws[32];
    int w = threadIdx.x >> 5, l = threadIdx.x & 31;
    if (l == 0) ws[w] = v;
    __syncthreads();
    int nw = (int)(blockDim.x >> 5);
    v = (threadIdx.x < 32) ? ((l < nw) ? ws[l] : 0.0f) : 0.0f;
    if (w == 0) {
        #pragma unroll
        for (int o = 16; o; o >>= 1) v += __shfl_xor_sync(0xFFFFFFFFu, v, o);
    }
    return v;  // valid on thread 0
}

// ---------------------------------------------------------------------------
// Fused main kernel.
//   blocks [0, 512):   skel top-2 over one N-split (per b, 128 m's, split)
//   blocks [512,1024):  shape min over all M (per b, 128 n's) -> cd1 partials
// grid = 1024, block = 128
// ---------------------------------------------------------------------------
__global__ void __launch_bounds__(128) k_main(const float* __restrict__ shape,
                                              const float* __restrict__ skel) {
    __shared__ __align__(16) float sx[1024];
    __shared__ __align__(16) float sy[1024];
    __shared__ __align__(16) float sz[1024];

    const int bid = blockIdx.x;
    const int tid = threadIdx.x;

    if (bid < 512) {
        // ---------------- skel part ----------------
        const int b      = bid >> 5;
        const int r      = bid & 31;
        const int split  = r & 3;
        const int mchunk = r >> 2;
        const int nbase  = split * NT;

        for (int i = tid; i < NT; i += 128) {
            const float* p = shape + ((size_t)(b * NN + nbase + i)) * 6;
            sx[i] = p[0]; sy[i] = p[1]; sz[i] = p[2];
        }
        __syncthreads();

        const int m = mchunk * 128 + tid;
        const float* s = skel + ((size_t)(b * MM + m)) * 3;
        const u64 nqx = pk2(-s[0], -s[0]);
        const u64 nqy = pk2(-s[1], -s[1]);
        const u64 nqz = pk2(-s[2], -s[2]);

        unsigned c1a = ~0u, c2a = ~0u, c1b = ~0u, c2b = ~0u;
        unsigned c1c = ~0u, c2c = ~0u, c1d = ~0u, c2d = ~0u;

        const ulonglong2* x2 = (const ulonglong2*)sx;
        const ulonglong2* y2 = (const ulonglong2*)sy;
        const ulonglong2* z2 = (const ulonglong2*)sz;

        #pragma unroll 2
        for (int j = 0; j < NT; j += 4) {
            const int g = j >> 2;
            ulonglong2 xv = x2[g], yv = y2[g], zv = z2[g];
            u64 dx01 = addx2(nqx, xv.x), dx23 = addx2(nqx, xv.y);
            u64 dy01 = addx2(nqy, yv.x), dy23 = addx2(nqy, yv.y);
            u64 dz01 = addx2(nqz, zv.x), dz23 = addx2(nqz, zv.y);
            u64 q01 = mulx2(dz01, dz01);
            q01 = fmx2(dy01, dy01, q01);
            q01 = fmx2(dx01, dx01, q01);
            u64 q23 = mulx2(dz23, dz23);
            q23 = fmx2(dy23, dy23, q23);
            q23 = fmx2(dx23, dx23, q23);
            unsigned u0, u1, u2, u3;
            upku(q01, u0, u1);
            upku(q23, u2, u3);
            upd2(c1a, c2a, (u0 & KEY_MASK) | (unsigned)(j + 0));
            upd2(c1b, c2b, (u1 & KEY_MASK) | (unsigned)(j + 1));
            upd2(c1c, c2c, (u2 & KEY_MASK) | (unsigned)(j + 2));
            upd2(c1d, c2d, (u3 & KEY_MASK) | (unsigned)(j + 3));
        }
        upd2(c1a, c2a, c1b); upd2(c1a, c2a, c2b);
        upd2(c1a, c2a, c1c); upd2(c1a, c2a, c2c);
        upd2(c1a, c2a, c1d); upd2(c1a, c2a, c2d);

        const int idx = (b * MM + m) * NSPLIT + split;
        g_p1[idx] = c1a;
        g_p2[idx] = c2a;
    } else {
        // ---------------- shape part (cd1) ----------------
        const int sb     = bid - 512;
        const int b      = sb >> 5;
        const int nchunk = sb & 31;

        for (int i = tid; i < MM; i += 128) {
            const float* s = skel + ((size_t)(b * MM + i)) * 3;
            sx[i] = s[0]; sy[i] = s[1]; sz[i] = s[2];
        }
        __syncthreads();

        const int n = nchunk * 128 + tid;
        const float* p = shape + ((size_t)(b * NN + n)) * 6;
        const u64 nqx = pk2(-p[0], -p[0]);
        const u64 nqy = pk2(-p[1], -p[1]);
        const u64 nqz = pk2(-p[2], -p[2]);

        float m0 = 1e30f, m1 = 1e30f, m2 = 1e30f, m3 = 1e30f;

        const ulonglong2* x2 = (const ulonglong2*)sx;
        const ulonglong2* y2 = (const ulonglong2*)sy;
        const ulonglong2* z2 = (const ulonglong2*)sz;

        #pragma unroll 2
        for (int j = 0; j < MM; j += 4) {
            const int g = j >> 2;
            ulonglong2 xv = x2[g], yv = y2[g], zv = z2[g];
            u64 dx01 = addx2(nqx, xv.x), dx23 = addx2(nqx, xv.y);
            u64 dy01 = addx2(nqy, yv.x), dy23 = addx2(nqy, yv.y);
            u64 dz01 = addx2(nqz, zv.x), dz23 = addx2(nqz, zv.y);
            u64 q01 = mulx2(dz01, dz01);
            q01 = fmx2(dy01, dy01, q01);
            q01 = fmx2(dx01, dx01, q01);
            u64 q23 = mulx2(dz23, dz23);
            q23 = fmx2(dy23, dy23, q23);
            q23 = fmx2(dx23, dx23, q23);
            float f0, f1, f2, f3;
            upkf(q01, f0, f1);
            upkf(q23, f2, f3);
            m0 = fminf(m0, f0);
            m1 = fminf(m1, f1);
            m2 = fminf(m2, f2);
            m3 = fminf(m3, f3);
        }
        float dmin = fminf(fminf(m0, m1), fminf(m2, m3));
        float val  = 1e-4f * sqrtf(fmaxf(dmin, 1e-12f));

        float bsum = blockSum(val);
        if (tid == 0) g_ps[sb] = bsum;
    }
}

// ---------------------------------------------------------------------------
// Merge split partials per (b, m): cd2 + normal terms, then last-block-done
// finalization (sums all partials, writes the scalar output).
// grid = 256, block = 64
// ---------------------------------------------------------------------------
__global__ void __launch_bounds__(64) k_merge(const float* __restrict__ shape,
                                              const float* __restrict__ nori,
                                              float* __restrict__ out) {
    const int t = blockIdx.x * 64 + threadIdx.x;  // t = b*MM + m
    const int b = t >> 10;

    float d1 = 1e30f, d2v = 1e30f;
    int n1 = 0, n2 = 0;

    #pragma unroll
    for (int s = 0; s < NSPLIT; s++) {
        const int base = t * NSPLIT + s;
        #pragma unroll
        for (int which = 0; which < 2; which++) {
            unsigned key = which ? g_p2[base] : g_p1[base];
            float df = __uint_as_float(key & KEY_MASK);
            int   nn = (int)(key & IDX_MASK) + s * NT;
            if (df < d1)       { d2v = d1; n2 = n1; d1 = df; n1 = nn; }
            else if (df < d2v) { d2v = df; n2 = nn; }
        }
    }

    float cd = sqrtf(fmaxf(d1, 1e-12f));

    const float* nr = nori + (size_t)t * 3;
    const float* f1 = shape + ((size_t)(b * NN + n1)) * 6 + 3;
    const float* f2 = shape + ((size_t)(b * NN + n2)) * 6 + 3;
    float dot1 = nr[0] * f1[0] + nr[1] * f1[1] + nr[2] * f1[2];
    float dot2 = nr[0] * f2[0] + nr[1] * f2[1] + nr[2] * f2[2];

    float val = 1e-4f * cd + (0.001f / (float)BB) * 0.5f * (fabsf(dot1) + fabsf(dot2));

    float bsum = blockSum(val);

    __shared__ bool lastBlock;
    if (threadIdx.x == 0) {
        g_pm[blockIdx.x] = bsum;
        __threadfence();
        lastBlock = (atomicInc(&g_cnt, 255u) == 255u);
    }
    __syncthreads();

    if (lastBlock) {
        double acc = 0.0;
        for (int i = threadIdx.x; i < 512; i += 64) acc += (double)g_ps[i];
        for (int i = threadIdx.x; i < 256; i += 64) acc += (double)g_pm[i];
        #pragma unroll
        for (int o = 16; o; o >>= 1) acc += __shfl_xor_sync(0xFFFFFFFFu, acc, o);
        __shared__ double w2[2];
        if ((threadIdx.x & 31) == 0) w2[threadIdx.x >> 5] = acc;
        __syncthreads();
        if (threadIdx.x == 0) out[0] = (float)(w2[0] + w2[1]);
    }
}

extern "C" void kernel_launch(void* const* d_in, const int* in_sizes, int n_in,
                              void* d_out, int out_size) {
    const float* shape = (const float*)d_in[0];  // (B, N, 6)
    const float* skel  = (const float*)d_in[1];  // (B, M, 3)
    const float* nori  = (const float*)d_in[2];  // (B, M, 3)
    float* out = (float*)d_out;

    k_main<<<1024, 128>>>(shape, skel);
    k_merge<<<256, 64>>>(shape, nori, out);
}

// round 3
// speedup vs baseline: 1.3626x; 1.0807x over previous
#include <cuda_runtime.h>
#include <math.h>

#define BB 16
#define NN 4096
#define MM 1024
#define NSPLIT 4
#define NT (NN / NSPLIT)   // 1024

#define KEY_MASK 0xFFFFFC00u
#define IDX_MASK 0x000003FFu

typedef unsigned long long u64;

// scratch (static device globals: no allocation allowed)
__device__ unsigned int g_p1[BB * MM * NSPLIT];
__device__ unsigned int g_p2[BB * MM * NSPLIT];
__device__ float        g_ps[512];   // shape-part block partials
__device__ float        g_pm[64];    // merge-part block partials
__device__ unsigned int g_cnt = 0;   // self-resetting completion counter

// ---- packed f32x2 helpers ----
__device__ __forceinline__ u64 addx2(u64 a, u64 b) {
    u64 r; asm("add.rn.f32x2 %0,%1,%2;" : "=l"(r) : "l"(a), "l"(b)); return r;
}
__device__ __forceinline__ u64 mulx2(u64 a, u64 b) {
    u64 r; asm("mul.rn.f32x2 %0,%1,%2;" : "=l"(r) : "l"(a), "l"(b)); return r;
}
__device__ __forceinline__ u64 fmx2(u64 a, u64 b, u64 c) {
    u64 r; asm("fma.rn.f32x2 %0,%1,%2,%3;" : "=l"(r) : "l"(a), "l"(b), "l"(c)); return r;
}
__device__ __forceinline__ u64 pk2(float a, float b) {
    u64 r; asm("mov.b64 %0,{%1,%2};" : "=l"(r) : "f"(a), "f"(b)); return r;
}
__device__ __forceinline__ void upku(u64 v, unsigned& a, unsigned& b) {
    asm("mov.b64 {%0,%1},%2;" : "=r"(a), "=r"(b) : "l"(v));
}
__device__ __forceinline__ void upkf(u64 v, float& a, float& b) {
    asm("mov.b64 {%0,%1},%2;" : "=f"(a), "=f"(b) : "l"(v));
}

// branch-free top-2 update on packed keys (positive-float uint ordering)
__device__ __forceinline__ void upd2(unsigned& b1, unsigned& b2, unsigned k) {
    unsigned mx = max(k, b1);
    b2 = min(b2, mx);
    b1 = min(b1, k);
}

__device__ __forceinline__ float blockSum(float v) {
    #pragma unroll
    for (int o = 16; o; o >>= 1) v += __shfl_xor_sync(0xFFFFFFFFu, v, o);
    __shared__ float ws[32];
    int w = threadIdx.x >> 5, l = threadIdx.x & 31;
    if (l == 0) ws[w] = v;
    __syncthreads();
    int nw = (int)(blockDim.x >> 5);
    v = (threadIdx.x < 32) ? ((l < nw) ? ws[l] : 0.0f) : 0.0f;
    if (w == 0) {
        #pragma unroll
        for (int o = 16; o; o >>= 1) v += __shfl_xor_sync(0xFFFFFFFFu, v, o);
    }
    return v;  // valid on thread 0
}

// ---------------------------------------------------------------------------
// Fused main kernel.
//   blocks [0, 512):   skel top-2 over one N-split (direct (p-s)^2 keys)
//   blocks [512,1024): shape min over all M (Gram form) -> cd1 partials
// grid = 1024, block = 128
// ---------------------------------------------------------------------------
__global__ void __launch_bounds__(128) k_main(const float* __restrict__ shape,
                                              const float* __restrict__ skel) {
    __shared__ __align__(16) float sx[1024];
    __shared__ __align__(16) float sy[1024];
    __shared__ __align__(16) float sz[1024];
    __shared__ __align__(16) float sw[1024];

    const int bid = blockIdx.x;
    const int tid = threadIdx.x;

    if (bid < 512) {
        // ---------------- skel part (top-2 per m over one N split) ----------
        const int b      = bid >> 5;
        const int r      = bid & 31;
        const int split  = r & 3;
        const int mchunk = r >> 2;
        const int nbase  = split * NT;

        for (int i = tid; i < NT; i += 128) {
            const float* p = shape + ((size_t)(b * NN + nbase + i)) * 6;
            sx[i] = p[0]; sy[i] = p[1]; sz[i] = p[2];
        }
        __syncthreads();

        const int m = mchunk * 128 + tid;
        const float* s = skel + ((size_t)(b * MM + m)) * 3;
        const u64 nqx = pk2(-s[0], -s[0]);
        const u64 nqy = pk2(-s[1], -s[1]);
        const u64 nqz = pk2(-s[2], -s[2]);

        unsigned c1a = ~0u, c2a = ~0u, c1b = ~0u, c2b = ~0u;
        unsigned c1c = ~0u, c2c = ~0u, c1d = ~0u, c2d = ~0u;

        const ulonglong2* x2 = (const ulonglong2*)sx;
        const ulonglong2* y2 = (const ulonglong2*)sy;
        const ulonglong2* z2 = (const ulonglong2*)sz;

        #pragma unroll 2
        for (int j = 0; j < NT; j += 4) {
            const int g = j >> 2;
            ulonglong2 xv = x2[g], yv = y2[g], zv = z2[g];
            u64 dx01 = addx2(nqx, xv.x), dx23 = addx2(nqx, xv.y);
            u64 dy01 = addx2(nqy, yv.x), dy23 = addx2(nqy, yv.y);
            u64 dz01 = addx2(nqz, zv.x), dz23 = addx2(nqz, zv.y);
            u64 q01 = mulx2(dz01, dz01);
            q01 = fmx2(dy01, dy01, q01);
            q01 = fmx2(dx01, dx01, q01);
            u64 q23 = mulx2(dz23, dz23);
            q23 = fmx2(dy23, dy23, q23);
            q23 = fmx2(dx23, dx23, q23);
            unsigned u0, u1, u2, u3;
            upku(q01, u0, u1);
            upku(q23, u2, u3);
            upd2(c1a, c2a, (u0 & KEY_MASK) | (unsigned)(j + 0));
            upd2(c1b, c2b, (u1 & KEY_MASK) | (unsigned)(j + 1));
            upd2(c1c, c2c, (u2 & KEY_MASK) | (unsigned)(j + 2));
            upd2(c1d, c2d, (u3 & KEY_MASK) | (unsigned)(j + 3));
        }
        upd2(c1a, c2a, c1b); upd2(c1a, c2a, c2b);
        upd2(c1a, c2a, c1c); upd2(c1a, c2a, c2c);
        upd2(c1a, c2a, c1d); upd2(c1a, c2a, c2d);

        const int idx = (b * MM + m) * NSPLIT + split;
        g_p1[idx] = c1a;
        g_p2[idx] = c2a;
    } else {
        // ---------------- shape part (cd1, Gram form) ----------------------
        const int sb     = bid - 512;
        const int b      = sb >> 5;
        const int nchunk = sb & 31;

        for (int i = tid; i < MM; i += 128) {
            const float* s = skel + ((size_t)(b * MM + i)) * 3;
            float X = s[0], Y = s[1], Z = s[2];
            sx[i] = X; sy[i] = Y; sz[i] = Z;
            sw[i] = X * X + Y * Y + Z * Z;
        }
        __syncthreads();

        const int n = nchunk * 128 + tid;
        const float* p = shape + ((size_t)(b * NN + n)) * 6;
        const float px = p[0], py = p[1], pz = p[2];
        const float pp = px * px + py * py + pz * pz;  // |p|^2
        const u64 m2x = pk2(-2.0f * px, -2.0f * px);
        const u64 m2y = pk2(-2.0f * py, -2.0f * py);
        const u64 m2z = pk2(-2.0f * pz, -2.0f * pz);

        float m0 = 1e30f, m1 = 1e30f, m2 = 1e30f, m3 = 1e30f;

        const ulonglong2* x2 = (const ulonglong2*)sx;
        const ulonglong2* y2 = (const ulonglong2*)sy;
        const ulonglong2* z2 = (const ulonglong2*)sz;
        const ulonglong2* w2 = (const ulonglong2*)sw;

        #pragma unroll 2
        for (int j = 0; j < MM; j += 4) {
            const int g = j >> 2;
            ulonglong2 xv = x2[g], yv = y2[g], zv = z2[g], wv = w2[g];
            // t = |s|^2 - 2 p.s   (d^2 = |p|^2 + t, added once at the end)
            u64 t01 = fmx2(zv.x, m2z, wv.x);
            t01 = fmx2(yv.x, m2y, t01);
            t01 = fmx2(xv.x, m2x, t01);
            u64 t23 = fmx2(zv.y, m2z, wv.y);
            t23 = fmx2(yv.y, m2y, t23);
            t23 = fmx2(xv.y, m2x, t23);
            float f0, f1, f2, f3;
            upkf(t01, f0, f1);
            upkf(t23, f2, f3);
            m0 = fminf(m0, f0);
            m1 = fminf(m1, f1);
            m2 = fminf(m2, f2);
            m3 = fminf(m3, f3);
        }
        float tmin = fminf(fminf(m0, m1), fminf(m2, m3));
        float dmin = pp + tmin;
        float val  = 1e-4f * sqrtf(fmaxf(dmin, 1e-12f));

        float bsum = blockSum(val);
        if (tid == 0) g_ps[sb] = bsum;
    }
}

// ---------------------------------------------------------------------------
// Merge split partials per (b, m): cd2 + normal terms; last block finalizes.
// grid = 64, block = 256  (proven-fast geometry: 8 warps stacked per SM)
// ---------------------------------------------------------------------------
__global__ void __launch_bounds__(256) k_merge(const float* __restrict__ shape,
                                               const float* __restrict__ nori,
                                               float* __restrict__ out) {
    const int t = blockIdx.x * 256 + threadIdx.x;  // t = b*MM + m
    const int b = t >> 10;

    float d1 = 1e30f, d2v = 1e30f;
    int n1 = 0, n2 = 0;

    #pragma unroll
    for (int s = 0; s < NSPLIT; s++) {
        const int base = t * NSPLIT + s;
        #pragma unroll
        for (int which = 0; which < 2; which++) {
            unsigned key = which ? g_p2[base] : g_p1[base];
            float df = __uint_as_float(key & KEY_MASK);
            int   nn = (int)(key & IDX_MASK) + s * NT;
            if (df < d1)       { d2v = d1; n2 = n1; d1 = df; n1 = nn; }
            else if (df < d2v) { d2v = df; n2 = nn; }
        }
    }

    float cd = sqrtf(fmaxf(d1, 1e-12f));

    const float* nr = nori + (size_t)t * 3;
    const float* f1 = shape + ((size_t)(b * NN + n1)) * 6 + 3;
    const float* f2 = shape + ((size_t)(b * NN + n2)) * 6 + 3;
    float dot1 = nr[0] * f1[0] + nr[1] * f1[1] + nr[2] * f1[2];
    float dot2 = nr[0] * f2[0] + nr[1] * f2[1] + nr[2] * f2[2];

    float val = 1e-4f * cd + (0.001f / (float)BB) * 0.5f * (fabsf(dot1) + fabsf(dot2));

    float bsum = blockSum(val);

    __shared__ bool lastBlock;
    if (threadIdx.x == 0) {
        g_pm[blockIdx.x] = bsum;
        __threadfence();
        lastBlock = (atomicInc(&g_cnt, 63u) == 63u);
    }
    __syncthreads();

    if (lastBlock) {
        double acc = 0.0;
        for (int i = threadIdx.x; i < 512; i += 256) acc += (double)g_ps[i];
        if (threadIdx.x < 64) acc += (double)g_pm[threadIdx.x];
        #pragma unroll
        for (int o = 16; o; o >>= 1) acc += __shfl_xor_sync(0xFFFFFFFFu, acc, o);
        __shared__ double wsum[8];
        if ((threadIdx.x & 31) == 0) wsum[threadIdx.x >> 5] = acc;
        __syncthreads();
        if (threadIdx.x == 0) {
            double r = 0.0;
            #pragma unroll
            for (int i = 0; i < 8; i++) r += wsum[i];
            out[0] = (float)r;
        }
    }
}

extern "C" void kernel_launch(void* const* d_in, const int* in_sizes, int n_in,
                              void* d_out, int out_size) {
    const float* shape = (const float*)d_in[0];  // (B, N, 6)
    const float* skel  = (const float*)d_in[1];  // (B, M, 3)
    const float* nori  = (const float*)d_in[2];  // (B, M, 3)
    float* out = (float*)d_out;

    k_main<<<1024, 128>>>(shape, skel);
    k_merge<<<64, 256>>>(shape, nori, out);
}